// round 10
// baseline (speedup 1.0000x reference)
#include <cuda_runtime.h>
#include <math.h>

#define DD 6
#define SEQ 128
typedef unsigned long long u64;

__device__ __forceinline__ u64 pack2(float lo, float hi) {
    u64 r; asm("mov.b64 %0, {%1, %2};" : "=l"(r) : "f"(lo), "f"(hi)); return r;
}
__device__ __forceinline__ void unpack2(u64 v, float& lo, float& hi) {
    asm("mov.b64 {%0, %1}, %2;" : "=f"(lo), "=f"(hi) : "l"(v));
}
__device__ __forceinline__ u64 ffma2(u64 a, u64 b, u64 c) {
    u64 d; asm("fma.rn.f32x2 %0, %1, %2, %3;" : "=l"(d) : "l"(a), "l"(b), "l"(c)); return d;
}
__device__ __forceinline__ u64 fmul2(u64 a, u64 b) {
    u64 d; asm("mul.rn.f32x2 %0, %1, %2;" : "=l"(d) : "l"(a), "l"(b)); return d;
}
__device__ __forceinline__ u64 fadd2(u64 a, u64 b) {
    u64 d; asm("add.rn.f32x2 %0, %1, %2;" : "=l"(d) : "l"(a), "l"(b)); return d;
}
__device__ __forceinline__ float ex2f(float x) {
    float y; asm("ex2.approx.f32 %0, %1;" : "=f"(y) : "f"(x)); return y;
}
__device__ __forceinline__ float rcpf(float x) {
    float y; asm("rcp.approx.f32 %0, %1;" : "=f"(y) : "f"(x)); return y;
}

// weight-dup smem offsets (u64 units): each entry = (w,w)
#define WQ   0      // 108
#define BQ   108    // 18
#define WO   126    // 36
#define BO   162    // 6
#define W1   168    // 36
#define B1   204    // 6
#define W2   210    // 36
#define B2   246    // 6
#define L1W  252    // 6
#define L1B  258    // 6
#define L2W  264    // 6
#define L2B  270    // 6

// out-proj + residual + LN2 + FFN + residual, packed over 2 batches.
// __noinline__: confines epilogue register appetite to a call frame.
__device__ __noinline__ void epilogue2(
    const u64* __restrict__ o2,
    const float* __restrict__ x0, const float* __restrict__ x1,
    float* __restrict__ out0, float* __restrict__ out1,
    const u64* __restrict__ W)
{
    // reload x packed (L2 hit)
    u64 xp[DD];
#pragma unroll
    for (int k = 0; k < 3; ++k) {
        float2 a = ((const float2*)x0)[k];
        float2 b = ((const float2*)x1)[k];
        xp[2 * k]     = pack2(a.x, b.x);
        xp[2 * k + 1] = pack2(a.y, b.y);
    }
    // out-proj + residual
    u64 y2[DD];
#pragma unroll
    for (int d = 0; d < DD; ++d) {
        u64 a = W[BO + d];
#pragma unroll
        for (int i = 0; i < DD; ++i) a = ffma2(o2[i], W[WO + i * 6 + d], a);
        y2[d] = fadd2(xp[d], a);
    }
    // LN2 packed
    const u64 sixth2 = pack2(1.f / DD, 1.f / DD);
    const u64 neg2   = pack2(-1.f, -1.f);
    u64 sum2 = y2[0];
#pragma unroll
    for (int d = 1; d < DD; ++d) sum2 = fadd2(sum2, y2[d]);
    u64 m2 = fmul2(sum2, sixth2);
    u64 nm2 = fmul2(m2, neg2);
    u64 var2 = 0ull;
    u64 d2[DD];
#pragma unroll
    for (int d = 0; d < DD; ++d) {
        d2[d] = fadd2(y2[d], nm2);
        var2 = ffma2(d2[d], d2[d], var2);
    }
    float vA, vB;
    unpack2(fmul2(var2, sixth2), vA, vB);
    u64 rstd2 = pack2(rsqrtf(vA + 1e-5f), rsqrtf(vB + 1e-5f));
    u64 h2[DD];
#pragma unroll
    for (int d = 0; d < DD; ++d)
        h2[d] = ffma2(fmul2(d2[d], rstd2), W[L2W + d], W[L2B + d]);
    // FFN
    u64 g2[DD];
#pragma unroll
    for (int d = 0; d < DD; ++d) {
        u64 a = W[B1 + d];
#pragma unroll
        for (int i = 0; i < DD; ++i) a = ffma2(h2[i], W[W1 + i * 6 + d], a);
        float aA, aB;
        unpack2(a, aA, aB);
        g2[d] = pack2(aA * normcdff(aA), aB * normcdff(aB));   // exact gelu
    }
    float r0[DD], r1[DD];
#pragma unroll
    for (int d = 0; d < DD; ++d) {
        u64 a = W[B2 + d];
#pragma unroll
        for (int i = 0; i < DD; ++i) a = ffma2(g2[i], W[W2 + i * 6 + d], a);
        u64 f = fadd2(y2[d], a);
        unpack2(f, r0[d], r1[d]);
    }
#pragma unroll
    for (int k = 0; k < 3; ++k) {
        ((float2*)out0)[k] = make_float2(r0[2 * k], r0[2 * k + 1]);
        ((float2*)out1)[k] = make_float2(r1[2 * k], r1[2 * k + 1]);
    }
}

__global__ __launch_bounds__(256, 3) void block_ffn_kernel(
    const float* __restrict__ x,
    const float* __restrict__ ln1_w, const float* __restrict__ ln1_b,
    const float* __restrict__ wqkv,  const float* __restrict__ bqkv,
    const float* __restrict__ wo,    const float* __restrict__ bo,
    const float* __restrict__ ln2_w, const float* __restrict__ ln2_b,
    const float* __restrict__ w1,    const float* __restrict__ b1,
    const float* __restrict__ w2,    const float* __restrict__ b2,
    float* __restrict__ out)
{
    // 2 batch-pairs per block; per pair: 128 tokens x 12 u64 (k0..5,v0..5),
    // each u64 = (batch0, batch1)
    __shared__ __align__(16) u64 s_kv[2 * SEQ * 12];   // 24 KB
    __shared__ u64 s_wd[276];                          // duplicated weights

    const int t    = threadIdx.x;
    const int pair = t >> 7;          // which batch-pair in block
    const int i    = t & 127;         // my token
    const int b0   = blockIdx.x * 4 + pair * 2;   // lane-0 batch
    // lane-1 batch = b0 + 1

    // ---- stage duplicated weights ----
    if (t < 108)      s_wd[WQ + t]        = pack2(wqkv[t], wqkv[t]);
    else if (t < 126) s_wd[BQ + t - 108]  = pack2(bqkv[t - 108], bqkv[t - 108]);
    else if (t < 162) s_wd[WO + t - 126]  = pack2(wo[t - 126], wo[t - 126]);
    else if (t < 168) s_wd[BO + t - 162]  = pack2(bo[t - 162], bo[t - 162]);
    else if (t < 204) s_wd[W1 + t - 168]  = pack2(w1[t - 168], w1[t - 168]);
    else if (t < 210) s_wd[B1 + t - 204]  = pack2(b1[t - 204], b1[t - 204]);
    else if (t < 246) s_wd[W2 + t - 210]  = pack2(w2[t - 210], w2[t - 210]);
    else if (t < 252) s_wd[B2 + t - 246]  = pack2(b2[t - 246], b2[t - 246]);
    if (t < DD) {
        s_wd[L1W + t] = pack2(ln1_w[t], ln1_w[t]);
        s_wd[L1B + t] = pack2(ln1_b[t], ln1_b[t]);
        s_wd[L2W + t] = pack2(ln2_w[t], ln2_w[t]);
        s_wd[L2B + t] = pack2(ln2_b[t], ln2_b[t]);
    }

    const float* x0 = x + ((long)b0 * SEQ + i) * DD;
    const float* x1 = x0 + SEQ * DD;     // batch b0+1, same token

    // ---- load x packed over batches ----
    u64 xp[DD];
#pragma unroll
    for (int k = 0; k < 3; ++k) {
        float2 a = ((const float2*)x0)[k];
        float2 b = ((const float2*)x1)[k];
        xp[2 * k]     = pack2(a.x, b.x);
        xp[2 * k + 1] = pack2(a.y, b.y);
    }

    // ---- LN1 packed ----
    const u64 sixth2 = pack2(1.f / DD, 1.f / DD);
    const u64 neg2   = pack2(-1.f, -1.f);
    u64 sum2 = xp[0];
#pragma unroll
    for (int d = 1; d < DD; ++d) sum2 = fadd2(sum2, xp[d]);
    u64 m2 = fmul2(sum2, sixth2);
    u64 nm2 = fmul2(m2, neg2);
    u64 var2 = 0ull;
    u64 dmu[DD];
#pragma unroll
    for (int d = 0; d < DD; ++d) {
        dmu[d] = fadd2(xp[d], nm2);
        var2 = ffma2(dmu[d], dmu[d], var2);
    }
    float vA, vB;
    unpack2(fmul2(var2, sixth2), vA, vB);
    u64 rstd2 = pack2(rsqrtf(vA + 1e-5f), rsqrtf(vB + 1e-5f));

    __syncthreads();   // weights staged

    u64 h2[DD];
#pragma unroll
    for (int d = 0; d < DD; ++d)
        h2[d] = ffma2(fmul2(dmu[d], rstd2), s_wd[L1W + d], s_wd[L1B + d]);

    // ---- QKV projection; fold 1/sqrt(D)*log2(e) into q ----
    const float SCL = 0.58897937652f;   // (1/sqrt6)*log2(e)
    const u64 scl2 = pack2(SCL, SCL);
    u64 q2[DD];
#pragma unroll
    for (int j = 0; j < DD; ++j) {
        u64 a = s_wd[BQ + j];
#pragma unroll
        for (int d = 0; d < DD; ++d) a = ffma2(h2[d], s_wd[WQ + d * 18 + j], a);
        q2[j] = fmul2(a, scl2);
    }
    {
        u64* my = s_kv + (pair * SEQ + i) * 12;
#pragma unroll
        for (int j = 0; j < 12; ++j) {
            u64 a = s_wd[BQ + 6 + j];
#pragma unroll
            for (int d = 0; d < DD; ++d) a = ffma2(h2[d], s_wd[WQ + d * 18 + 6 + j], a);
            my[j] = a;
        }
    }

    __syncthreads();   // all K/V visible

    // ---- causal attention: lanes = 2 batches, no masking needed ----
    const u64* kvb = s_kv + pair * SEQ * 12;
    u64 acc0 = 0ull, acc1 = 0ull, acc2_ = 0ull, acc3 = 0ull, acc4 = 0ull, acc5 = 0ull;
    u64 l2 = 0ull;

#pragma unroll 2
    for (int j = 0; j <= i; ++j) {
        const ulonglong2* p = (const ulonglong2*)(kvb + j * 12);
        ulonglong2 K01 = p[0], K23 = p[1], K45 = p[2];
        ulonglong2 V01 = p[3], V23 = p[4], V45 = p[5];
        u64 s2 = ffma2(q2[5], K45.y,
                 ffma2(q2[4], K45.x,
                 ffma2(q2[3], K23.y,
                 ffma2(q2[2], K23.x,
                 ffma2(q2[1], K01.y,
                 fmul2(q2[0], K01.x))))));
        float sA, sB;
        unpack2(s2, sA, sB);
        u64 p2 = pack2(ex2f(sA), ex2f(sB));
        l2 = fadd2(l2, p2);
        acc0 = ffma2(p2, V01.x, acc0);
        acc1 = ffma2(p2, V01.y, acc1);
        acc2_ = ffma2(p2, V23.x, acc2_);
        acc3 = ffma2(p2, V23.y, acc3);
        acc4 = ffma2(p2, V45.x, acc4);
        acc5 = ffma2(p2, V45.y, acc5);
    }

    float lA, lB;
    unpack2(l2, lA, lB);
    u64 inv2 = pack2(rcpf(lA), rcpf(lB));
    u64 o2[DD];
    o2[0] = fmul2(acc0, inv2);
    o2[1] = fmul2(acc1, inv2);
    o2[2] = fmul2(acc2_, inv2);
    o2[3] = fmul2(acc3, inv2);
    o2[4] = fmul2(acc4, inv2);
    o2[5] = fmul2(acc5, inv2);

    float* out0 = out + ((long)b0 * SEQ + i) * DD;
    epilogue2(o2, x0, x1, out0, out0 + SEQ * DD, s_wd);
}

extern "C" void kernel_launch(void* const* d_in, const int* in_sizes, int n_in,
                              void* d_out, int out_size) {
    const float* x     = (const float*)d_in[0];
    const float* ln1_w = (const float*)d_in[1];
    const float* ln1_b = (const float*)d_in[2];
    const float* wqkv  = (const float*)d_in[3];
    const float* bqkv  = (const float*)d_in[4];
    const float* wo    = (const float*)d_in[5];
    const float* bo    = (const float*)d_in[6];
    const float* ln2_w = (const float*)d_in[7];
    const float* ln2_b = (const float*)d_in[8];
    const float* w1    = (const float*)d_in[9];
    const float* b1    = (const float*)d_in[10];
    const float* w2    = (const float*)d_in[11];
    const float* b2    = (const float*)d_in[12];
    float* out = (float*)d_out;

    const int B = in_sizes[0] / (SEQ * DD);   // 8192
    block_ffn_kernel<<<B / 4, 256>>>(x, ln1_w, ln1_b, wqkv, bqkv, wo, bo,
                                     ln2_w, ln2_b, w1, b1, w2, b2, out);
}